// round 16
// baseline (speedup 1.0000x reference)
#include <cuda_runtime.h>
#include <cstdint>

// LocalConvolutionMix: per-pixel local conv, 3x3(pad1) + 5x5(pad2) branches.
// x:  [4, 256, 56, 56] f32
// w1: [4, 1, 32, 9,  56, 56]
// w2: [4, 1, 32, 25, 56, 56]
// out:[4, 2, 1, 256, 56, 56]
//
// TMA weight streaming: for each tap, the block's weights w[tap][h0:h0+8][0:56]
// are one contiguous 1792B chunk. A double-buffered cp.async.bulk + mbarrier
// pipeline (stage = ki row: 5 w2 taps + 3 w1 taps on mid rows) replaces all
// per-thread weight LDGs. Compute body identical to the R14 champion.

#define N_    4
#define C_    256
#define H_    56
#define W_    56
#define WC_   32
#define GPB_  8
#define TH_   8
#define TW_   28
#define HW_   (H_*W_)
#define TCOL_ 64          // x smem row: cols 4..59 = x[0..55], halo 2,3,60,61

#define CHUNK_BYTES  (TH_*W_*4)    // 1792
#define CHUNK_FLOATS (TH_*W_)      // 448

// dynamic smem layout (bytes)
#define XS_BYTES  (GPB_*(TH_+4)*TCOL_*4)   // 24576
#define WB_OFF    XS_BYTES                  // weight ring: [2][8][448] floats
#define WB_BYTES  (2*8*CHUNK_BYTES)         // 28672
#define MB_OFF    (WB_OFF + WB_BYTES)       // 53248: two 8B mbarriers
#define SMEM_TOTAL (MB_OFF + 16)

__device__ __forceinline__ uint32_t smem_u32(const void* p) {
    uint32_t a;
    asm("{ .reg .u64 t; cvta.to.shared.u64 t, %1; cvt.u32.u64 %0, t; }"
        : "=r"(a) : "l"(p));
    return a;
}

#define MBAR_INIT(m, cnt) \
    asm volatile("mbarrier.init.shared.b64 [%0], %1;" :: "r"(m), "r"(cnt) : "memory")
#define MBAR_EXPECT_TX(m, bytes) \
    asm volatile("mbarrier.arrive.expect_tx.shared.b64 _, [%0], %1;" \
                 :: "r"(m), "r"(bytes) : "memory")
#define BULK_G2S(dst, src, bytes, m) \
    asm volatile("cp.async.bulk.shared::cta.global.mbarrier::complete_tx::bytes " \
                 "[%0], [%1], %2, [%3];" \
                 :: "r"(dst), "l"(src), "r"(bytes), "r"(m) : "memory")
#define MBAR_WAIT(m, parity) do {                                              \
    uint32_t _m = (m), _p = (parity);                                          \
    asm volatile(                                                              \
        "{\n\t.reg .pred P;\n\t"                                               \
        "WL_%=:\n\t"                                                           \
        "mbarrier.try_wait.parity.acquire.cta.shared::cta.b64 P, [%0], %1, 0x989680;\n\t" \
        "@P bra.uni WD_%=;\n\t"                                                \
        "bra.uni WL_%=;\n\t"                                                   \
        "WD_%=:\n\t}"                                                          \
        :: "r"(_m), "r"(_p) : "memory");                                       \
} while (0)

__global__ __launch_bounds__(TW_*TH_, 4)
void localconv_mix_kernel(const float* __restrict__ x,
                          const float* __restrict__ w1,
                          const float* __restrict__ w2,
                          float* __restrict__ out)
{
    extern __shared__ __align__(16) char smem[];
    float (*xs)[TH_ + 4][TCOL_] = (float (*)[TH_ + 4][TCOL_])smem;
    float* wb = (float*)(smem + WB_OFF);
    const uint32_t mb0 = smem_u32(smem + MB_OFF);
    const uint32_t mb1 = mb0 + 8;
    const uint32_t wb_u32 = smem_u32(smem + WB_OFF);

    const int tx = threadIdx.x;            // 0..27
    const int ty = threadIdx.y;            // 0..7
    const int h0 = blockIdx.x * TH_;
    const int v  = blockIdx.y;             // 0..31
    const int n  = blockIdx.z;
    const int tid = ty * TW_ + tx;         // 0..223

    // per-tap contiguous chunks for this block's pixel window
    const float* w2base = w2 + (n * WC_ + v) * 25 * HW_ + h0 * W_;
    const float* w1base = w1 + (n * WC_ + v) * 9  * HW_ + h0 * W_;

    // ---- producer prologue: stages ki=0 (buf0) and ki=1 (buf1) ----
    if (tid == 0) {
        MBAR_INIT(mb0, 1);
        MBAR_INIT(mb1, 1);
        asm volatile("fence.proxy.async.shared::cta;" ::: "memory");
        // ki=0: 5 w2 taps
        MBAR_EXPECT_TX(mb0, 5 * CHUNK_BYTES);
        #pragma unroll
        for (int j = 0; j < 5; j++)
            BULK_G2S(wb_u32 + j * CHUNK_BYTES, w2base + j * HW_,
                     CHUNK_BYTES, mb0);
        // ki=1: 5 w2 taps + 3 w1 taps
        MBAR_EXPECT_TX(mb1, 8 * CHUNK_BYTES);
        #pragma unroll
        for (int j = 0; j < 5; j++)
            BULK_G2S(wb_u32 + (8 + j) * CHUNK_BYTES, w2base + (5 + j) * HW_,
                     CHUNK_BYTES, mb1);
        #pragma unroll
        for (int j = 0; j < 3; j++)
            BULK_G2S(wb_u32 + (8 + 5 + j) * CHUNK_BYTES, w1base + j * HW_,
                     CHUNK_BYTES, mb1);
    }

    // ---- stage x tile (LDG path; overlaps the TMA prologue) ----
    if (tid < 96) {
        const int g = tid / 12;
        const int r = tid - g * 12;
        xs[g][r][2]  = 0.f; xs[g][r][3]  = 0.f;
        xs[g][r][60] = 0.f; xs[g][r][61] = 0.f;
    }
    {
        const int f4   = tid % 14;
        const int rowi = tid / 14;
        #pragma unroll
        for (int it = 0; it < 6; it++) {
            const int row = rowi + 16 * it;          // 0..95
            const int g = row / 12;
            const int r = row - g * 12;
            const int hh = h0 - 2 + r;
            float4 val = make_float4(0.f, 0.f, 0.f, 0.f);
            if (hh >= 0 && hh < H_) {
                const int c = g * WC_ + v;
                val = *(const float4*)(x + (((n * C_ + c) * H_ + hh) * W_ + 4 * f4));
            }
            *(float4*)&xs[g][r][4 + 4 * f4] = val;
        }
    }
    __syncthreads();   // x tile ready; also orders mbarrier init for all waiters

    const int w0 = 2 * tx;
    const int pix = (h0 + ty) * W_ + w0;
    const int woff = ty * W_ + w0;         // float2 offset inside a chunk

    float2 a1[GPB_], a2[GPB_];
    #pragma unroll
    for (int g = 0; g < GPB_; g++) {
        a1[g] = make_float2(0.f, 0.f);
        a2[g] = make_float2(0.f, 0.f);
    }

    #pragma unroll
    for (int ki = 0; ki < 5; ki++) {
        const int s = ki & 1;
        MBAR_WAIT(s ? mb1 : mb0, (ki >> 1) & 1);

        // weights for this stage from smem (conflict-free LDS.64)
        const float* wrow = wb + (s * 8) * CHUNK_FLOATS + woff;
        float2 w2c[5];
        #pragma unroll
        for (int j = 0; j < 5; j++)
            w2c[j] = *(const float2*)(wrow + j * CHUNK_FLOATS);

        const bool mid = (ki >= 1 && ki <= 3);
        float2 w1c[3];
        if (mid) {
            #pragma unroll
            for (int j = 0; j < 3; j++)
                w1c[j] = *(const float2*)(wrow + (5 + j) * CHUNK_FLOATS);
        }

        #pragma unroll
        for (int g = 0; g < GPB_; g++) {
            // window x[w0-2 .. w0+3] at smem cols w0+2 .. w0+7 (8B aligned)
            const float* row = &xs[g][ty + ki][w0 + 2];
            const float2 p01 = *(const float2*)(row + 0);
            const float2 p23 = *(const float2*)(row + 2);
            const float2 p45 = *(const float2*)(row + 4);
            const float x0 = p01.x, x1 = p01.y, x2 = p23.x,
                        x3 = p23.y, x4 = p45.x, x5 = p45.y;

            a2[g].x = fmaf(w2c[0].x, x0, a2[g].x);
            a2[g].y = fmaf(w2c[0].y, x1, a2[g].y);
            a2[g].x = fmaf(w2c[1].x, x1, a2[g].x);
            a2[g].y = fmaf(w2c[1].y, x2, a2[g].y);
            a2[g].x = fmaf(w2c[2].x, x2, a2[g].x);
            a2[g].y = fmaf(w2c[2].y, x3, a2[g].y);
            a2[g].x = fmaf(w2c[3].x, x3, a2[g].x);
            a2[g].y = fmaf(w2c[3].y, x4, a2[g].y);
            a2[g].x = fmaf(w2c[4].x, x4, a2[g].x);
            a2[g].y = fmaf(w2c[4].y, x5, a2[g].y);

            if (mid) {
                a1[g].x = fmaf(w1c[0].x, x1, a1[g].x);
                a1[g].y = fmaf(w1c[0].y, x2, a1[g].y);
                a1[g].x = fmaf(w1c[1].x, x2, a1[g].x);
                a1[g].y = fmaf(w1c[1].y, x3, a1[g].y);
                a1[g].x = fmaf(w1c[2].x, x3, a1[g].x);
                a1[g].y = fmaf(w1c[2].y, x4, a1[g].y);
            }
        }

        if (ki < 4) {
            __syncthreads();   // all threads done reading buffer s
            if (ki <= 2 && tid == 0) {
                const int kn = ki + 2;              // refill buffer s for kn
                const uint32_t m = s ? mb1 : mb0;
                const uint32_t dst = wb_u32 + (s * 8) * CHUNK_BYTES;
                const bool nmid = (kn >= 1 && kn <= 3);
                MBAR_EXPECT_TX(m, (nmid ? 8 : 5) * CHUNK_BYTES);
                #pragma unroll
                for (int j = 0; j < 5; j++)
                    BULK_G2S(dst + j * CHUNK_BYTES, w2base + (kn * 5 + j) * HW_,
                             CHUNK_BYTES, m);
                if (nmid) {
                    #pragma unroll
                    for (int j = 0; j < 3; j++)
                        BULK_G2S(dst + (5 + j) * CHUNK_BYTES,
                                 w1base + ((kn - 1) * 3 + j) * HW_,
                                 CHUNK_BYTES, m);
                }
            }
        }
    }

    // streaming stores: output never re-read
    #pragma unroll
    for (int g = 0; g < GPB_; g++) {
        const int c = g * WC_ + v;
        __stcs((float2*)&out[((n * 2 + 0) * C_ + c) * HW_ + pix], a1[g]);
        __stcs((float2*)&out[((n * 2 + 1) * C_ + c) * HW_ + pix], a2[g]);
    }
}

extern "C" void kernel_launch(void* const* d_in, const int* in_sizes, int n_in,
                              void* d_out, int out_size)
{
    const float* x  = (const float*)d_in[0];
    const float* w1 = (const float*)d_in[1];
    const float* w2 = (const float*)d_in[2];
    float* out = (float*)d_out;

    cudaFuncSetAttribute(localconv_mix_kernel,
                         cudaFuncAttributeMaxDynamicSharedMemorySize, SMEM_TOTAL);

    dim3 block(TW_, TH_);          // 224 threads
    dim3 grid(H_ / TH_, WC_, N_);  // (7, 32, 4) = 896 blocks
    localconv_mix_kernel<<<grid, block, SMEM_TOTAL>>>(x, w1, w2, out);
}

// round 17
// speedup vs baseline: 1.0135x; 1.0135x over previous
#include <cuda_runtime.h>

// LocalConvolutionMix: per-pixel local conv, 3x3(pad1) + 5x5(pad2) branches.
// x:  [4, 256, 56, 56] f32
// w1: [4, 1, 32, 9,  56, 56]
// w2: [4, 1, 32, 25, 56, 56]
// out:[4, 2, 1, 256, 56, 56]
//
// Consolidated champion (best-measured pieces of rounds 9-15):
//  - block (28,8)=224 thr; thread = 2 adjacent W px x 8 channel groups x 2
//    branches; one block per (h-tile, v, n) -> weights hit DRAM exactly once
//  - depth-2 register pipeline on the w2 stream (rows ki+1, ki+2 in flight),
//    row-exact depth-1 pipeline on w1  [best ncu time of session]
//  - default-cache __ldg weight loads (ldcs measured slower)
//  - halo-first staging order, float4 x staging, full prologue L2 prefetch
//  - streaming output stores; 3 blocks/SM -> 896 blocks = 2.02 waves

#define N_    4
#define C_    256
#define H_    56
#define W_    56
#define WC_   32
#define GPB_  8
#define TH_   8
#define TW_   28
#define HW_   (H_*W_)
#define TCOL_ 64        // smem row: cols 4..59 = x[0..55], halo at 2,3,60,61

#define PF_L2(p) asm volatile("prefetch.global.L2 [%0];" :: "l"(p))

__global__ __launch_bounds__(TW_*TH_, 3)
void localconv_mix_kernel(const float* __restrict__ x,
                          const float* __restrict__ w1,
                          const float* __restrict__ w2,
                          float* __restrict__ out)
{
    __shared__ __align__(16) float xs[GPB_][TH_ + 4][TCOL_];

    const int tx = threadIdx.x;            // 0..27
    const int ty = threadIdx.y;            // 0..7
    const int h0 = blockIdx.x * TH_;
    const int v  = blockIdx.y;             // 0..31
    const int n  = blockIdx.z;

    const int tid = ty * TW_ + tx;         // 0..223

    // ---- halo zeroing first (independent of the x loads) ----
    if (tid < 96) {
        const int g = tid / 12;
        const int r = tid - g * 12;
        xs[g][r][2]  = 0.f; xs[g][r][3]  = 0.f;
        xs[g][r][60] = 0.f; xs[g][r][61] = 0.f;
    }

    // ---- stage x tile: aligned float4 interior ----
    {
        const int f4   = tid % 14;         // float4 index in row (0..13)
        const int rowi = tid / 14;         // 0..15
        #pragma unroll
        for (int it = 0; it < 6; it++) {
            const int row = rowi + 16 * it;          // 0..95
            const int g = row / 12;
            const int r = row - g * 12;
            const int hh = h0 - 2 + r;
            float4 val = make_float4(0.f, 0.f, 0.f, 0.f);
            if (hh >= 0 && hh < H_) {
                const int c = g * WC_ + v;
                val = *(const float4*)(x + (((n * C_ + c) * H_ + hh) * W_ + 4 * f4));
            }
            *(float4*)&xs[g][r][4 + 4 * f4] = val;
        }
    }

    const int h  = h0 + ty;
    const int w0 = 2 * tx;
    const int pix = h * W_ + w0;

    const float* w2p = w2 + (n * WC_ + v) * 25 * HW_ + pix;
    const float* w1p = w1 + (n * WC_ + v) * 9  * HW_ + pix;

    // full-depth prologue L2 prefetch (overlaps the staging barrier)
    #pragma unroll
    for (int j = 0; j < 15; j++) { PF_L2(w2p + (10 + j) * HW_); }
    #pragma unroll
    for (int j = 0; j < 9; j++)  { PF_L2(w1p + j * HW_); }

    __syncthreads();

    float2 a1[GPB_], a2[GPB_];
    #pragma unroll
    for (int g = 0; g < GPB_; g++) {
        a1[g] = make_float2(0.f, 0.f);
        a2[g] = make_float2(0.f, 0.f);
    }

    // --- depth-2 pipeline on w2 (rows ki+1, ki+2 in flight), w1 row-exact ---
    float2 w2c[5], w2n[5], w1c[3];
    #pragma unroll
    for (int j = 0; j < 5; j++)
        w2c[j] = __ldg((const float2*)(w2p + j * HW_));          // w2 row 0
    #pragma unroll
    for (int j = 0; j < 5; j++)
        w2n[j] = __ldg((const float2*)(w2p + (5 + j) * HW_));    // w2 row 1
    #pragma unroll
    for (int j = 0; j < 3; j++)
        w1c[j] = __ldg((const float2*)(w1p + j * HW_));          // w1 row 0 (ki=1)

    #pragma unroll
    for (int ki = 0; ki < 5; ki++) {
        float2 w2nn[5], w1n[3];
        if (ki < 3) {
            #pragma unroll
            for (int j = 0; j < 5; j++)
                w2nn[j] = __ldg((const float2*)(w2p + ((ki + 2) * 5 + j) * HW_));
        }
        if (ki == 1 || ki == 2) {              // w1 row ki, consumed at ki+1
            #pragma unroll
            for (int j = 0; j < 3; j++)
                w1n[j] = __ldg((const float2*)(w1p + (ki * 3 + j) * HW_));
        }

        const bool mid = (ki >= 1 && ki <= 3);

        #pragma unroll
        for (int g = 0; g < GPB_; g++) {
            // window x[w0-2 .. w0+3] at smem cols w0+2 .. w0+7 (8B aligned)
            const float* row = &xs[g][ty + ki][w0 + 2];
            const float2 p01 = *(const float2*)(row + 0);
            const float2 p23 = *(const float2*)(row + 2);
            const float2 p45 = *(const float2*)(row + 4);
            const float x0 = p01.x, x1 = p01.y, x2 = p23.x,
                        x3 = p23.y, x4 = p45.x, x5 = p45.y;

            a2[g].x = fmaf(w2c[0].x, x0, a2[g].x);
            a2[g].y = fmaf(w2c[0].y, x1, a2[g].y);
            a2[g].x = fmaf(w2c[1].x, x1, a2[g].x);
            a2[g].y = fmaf(w2c[1].y, x2, a2[g].y);
            a2[g].x = fmaf(w2c[2].x, x2, a2[g].x);
            a2[g].y = fmaf(w2c[2].y, x3, a2[g].y);
            a2[g].x = fmaf(w2c[3].x, x3, a2[g].x);
            a2[g].y = fmaf(w2c[3].y, x4, a2[g].y);
            a2[g].x = fmaf(w2c[4].x, x4, a2[g].x);
            a2[g].y = fmaf(w2c[4].y, x5, a2[g].y);

            if (mid) {
                a1[g].x = fmaf(w1c[0].x, x1, a1[g].x);
                a1[g].y = fmaf(w1c[0].y, x2, a1[g].y);
                a1[g].x = fmaf(w1c[1].x, x2, a1[g].x);
                a1[g].y = fmaf(w1c[1].y, x3, a1[g].y);
                a1[g].x = fmaf(w1c[2].x, x3, a1[g].x);
                a1[g].y = fmaf(w1c[2].y, x4, a1[g].y);
            }
        }

        // rotate pipelines (fully unrolled -> register renames)
        #pragma unroll
        for (int j = 0; j < 5; j++) { w2c[j] = w2n[j]; w2n[j] = w2nn[j]; }
        if (ki == 1 || ki == 2) {
            #pragma unroll
            for (int j = 0; j < 3; j++) w1c[j] = w1n[j];
        }
    }

    // streaming stores: output never re-read, keep L2 for weights/x
    #pragma unroll
    for (int g = 0; g < GPB_; g++) {
        const int c = g * WC_ + v;
        __stcs((float2*)&out[((n * 2 + 0) * C_ + c) * HW_ + pix], a1[g]);
        __stcs((float2*)&out[((n * 2 + 1) * C_ + c) * HW_ + pix], a2[g]);
    }
}

extern "C" void kernel_launch(void* const* d_in, const int* in_sizes, int n_in,
                              void* d_out, int out_size)
{
    const float* x  = (const float*)d_in[0];
    const float* w1 = (const float*)d_in[1];
    const float* w2 = (const float*)d_in[2];
    float* out = (float*)d_out;

    dim3 block(TW_, TH_);          // 224 threads
    dim3 grid(H_ / TH_, WC_, N_);  // (7, 32, 4) = 896 blocks
    localconv_mix_kernel<<<grid, block>>>(x, w1, w2, out);
}